// round 2
// baseline (speedup 1.0000x reference)
#include <cuda_runtime.h>

#define T_STEPS 1000
#define BATCH   1024
#define IN_DIM  80
#define HID     128
#define OUT_DIM 10

// Precomputed input GEMM: xw[t][b][h] = sum_k x[t][b][k] * w_in[h][k]
__device__ float g_xw[(size_t)T_STEPS * BATCH * HID];   // 524 MB (BSS)
__device__ float g_coef[T_STEPS];

// ---------------------------------------------------------------------------
// Readout coefficients: vo_final = sum_t c_t * (z_t @ w_out^T)
//   c_u = a_u + 0.8*c_{u+1},  a_u = 0.1 * 0.9^{T-1-u}
// ---------------------------------------------------------------------------
__global__ void coef_kernel() {
    if (threadIdx.x == 0) {
        double c = 0.0, p = 1.0;
        for (int u = T_STEPS - 1; u >= 0; --u) {
            double a = 0.1 * p;
            c = a + 0.8 * c;
            g_coef[u] = (float)c;
            p *= 0.9;
        }
    }
}

// ---------------------------------------------------------------------------
// Input GEMM: (T*B, IN) @ (IN, H) -> g_xw, fp32, serial ascending-k FFMA per
// output element (bitwise-matches a serial cuBLAS SIMT sgemm chain).
// ---------------------------------------------------------------------------
#define XS_STR 84
#define WS_STR 81
#define GEMM_SMEM ((128 * XS_STR + 128 * WS_STR) * 4)

__global__ __launch_bounds__(256, 2)
void gemm_in(const float* __restrict__ x, const float* __restrict__ w) {
    extern __shared__ float sm[];
    float* xs = sm;                 // [128][XS_STR]
    float* ws = sm + 128 * XS_STR;  // [128][WS_STR]
    int tid = threadIdx.x;
    size_t rowbase = (size_t)blockIdx.x * 128;

    const float4* xg = (const float4*)(x + rowbase * IN_DIM);
#pragma unroll
    for (int it = 0; it < 10; ++it) {
        int e = tid + it * 256;
        int row = e / 20, c4 = e % 20;
        float4 v = xg[e];
        *(float4*)&xs[row * XS_STR + c4 * 4] = v;
    }
    for (int e = tid; e < HID * IN_DIM; e += 256)
        ws[(e / IN_DIM) * WS_STR + (e % IN_DIM)] = w[e];
    __syncthreads();

    int mrow = (tid >> 4) * 8;
    int mcol = tid & 15;
    float acc[8][8];
#pragma unroll
    for (int i = 0; i < 8; i++)
#pragma unroll
        for (int j = 0; j < 8; j++) acc[i][j] = 0.f;

#pragma unroll 4
    for (int k = 0; k < IN_DIM; ++k) {
        float a[8], bb[8];
#pragma unroll
        for (int i = 0; i < 8; i++) a[i] = xs[(mrow + i) * XS_STR + k];
#pragma unroll
        for (int j = 0; j < 8; j++) bb[j] = ws[(mcol + 16 * j) * WS_STR + k];
#pragma unroll
        for (int i = 0; i < 8; i++)
#pragma unroll
            for (int j = 0; j < 8; j++)
                acc[i][j] = fmaf(a[i], bb[j], acc[i][j]);
    }

    float* op = g_xw + rowbase * HID;
#pragma unroll
    for (int i = 0; i < 8; i++)
#pragma unroll
        for (int j = 0; j < 8; j++)
            op[(mrow + i) * HID + mcol + 16 * j] = acc[i][j];
}

// ---------------------------------------------------------------------------
// Persistent simulation: one warp per batch element, 1000 steps in registers.
// State layout: lane holds h = r*32 + lane for r = 0..3. This makes draining
// ballot masks m0,m1,m2,m3 (each ascending bit order) exactly ascending-k
// order k=0..127 — matching a serial GEMM reduction chain bitwise.
// Recurrent sum R accumulated SEPARATELY from 0, then i = (i_dec + xw) + R,
// matching the reference's (i_dec + A) + R association.
// Shared w_rec^T pre-permuted: wr4[k*32+lane] = {wrec[lane][k], wrec[32+lane][k],
// wrec[64+lane][k], wrec[96+lane][k]} so one float4/LDS per spiking column.
// ---------------------------------------------------------------------------
#define SIM_SMEM ((HID * HID + T_STEPS + OUT_DIM * HID) * 4)

__global__ __launch_bounds__(256, 1)
void sim_kernel(const float* __restrict__ wrec, const float* __restrict__ wout,
                float* __restrict__ out) {
    extern __shared__ float sm[];
    float* wrp = sm;                 // permuted w_rec^T, 128*128
    float* cf  = wrp + HID * HID;    // [1000]
    float* wo  = cf + T_STEPS;       // [10][128]
    int tid = threadIdx.x, lane = tid & 31, wid = tid >> 5;
    int b = blockIdx.x * 8 + wid;

    // wrp[k*128 + ln*4 + r] = wrec[(r*32+ln)*128 + k]
    for (int e = tid; e < HID * HID; e += 256) {
        int k = e >> 7, j = e & 127;   // j = ln*4 + r
        int ln = j >> 2, r = j & 3;
        wrp[e] = wrec[(r * 32 + ln) * HID + k];
    }
    for (int e = tid; e < T_STEPS; e += 256) cf[e] = g_coef[e];
    for (int e = tid; e < OUT_DIM * HID; e += 256) wo[e] = wout[e];
    __syncthreads();

    float v0 = 0.f, v1 = 0.f, v2 = 0.f, v3 = 0.f;
    float i0 = 0.f, i1 = 0.f, i2 = 0.f, i3 = 0.f;
    float a0 = 0.f, a1 = 0.f, a2 = 0.f, a3 = 0.f;

    const float* xwp = g_xw + (size_t)b * HID + lane;
    const size_t tstride = (size_t)BATCH * HID;
    const float4* wr4 = (const float4*)wrp;  // column k: wr4[k*32 + lane]

    float xn0 = xwp[0], xn1 = xwp[32], xn2 = xwp[64], xn3 = xwp[96];

    for (int t = 0; t < T_STEPS; ++t) {
        float xc0 = xn0, xc1 = xn1, xc2 = xn2, xc3 = xn3;
        if (t + 1 < T_STEPS) {
            const float* p = xwp + (size_t)(t + 1) * tstride;
            xn0 = p[0]; xn1 = p[32]; xn2 = p[64]; xn3 = p[96];
        }
        float ct = cf[t];

        // v_dec = v + 0.1*((0 - v) + i)
        float vd0 = __fadd_rn(v0, __fmul_rn(0.1f, __fadd_rn(__fsub_rn(0.f, v0), i0)));
        float vd1 = __fadd_rn(v1, __fmul_rn(0.1f, __fadd_rn(__fsub_rn(0.f, v1), i1)));
        float vd2 = __fadd_rn(v2, __fmul_rn(0.1f, __fadd_rn(__fsub_rn(0.f, v2), i2)));
        float vd3 = __fadd_rn(v3, __fmul_rn(0.1f, __fadd_rn(__fsub_rn(0.f, v3), i3)));
        // i_dec = i - 0.2*i
        float id0 = __fsub_rn(i0, __fmul_rn(0.2f, i0));
        float id1 = __fsub_rn(i1, __fmul_rn(0.2f, i1));
        float id2 = __fsub_rn(i2, __fmul_rn(0.2f, i2));
        float id3 = __fsub_rn(i3, __fmul_rn(0.2f, i3));
        // spikes
        bool z0 = __fsub_rn(vd0, 1.0f) > 0.0f;
        bool z1 = __fsub_rn(vd1, 1.0f) > 0.0f;
        bool z2 = __fsub_rn(vd2, 1.0f) > 0.0f;
        bool z3 = __fsub_rn(vd3, 1.0f) > 0.0f;
        // reset
        v0 = z0 ? 0.0f : vd0;
        v1 = z1 ? 0.0f : vd1;
        v2 = z2 ? 0.0f : vd2;
        v3 = z3 ? 0.0f : vd3;
        // readout fold
        if (z0) a0 = __fadd_rn(a0, ct);
        if (z1) a1 = __fadd_rn(a1, ct);
        if (z2) a2 = __fadd_rn(a2, ct);
        if (z3) a3 = __fadd_rn(a3, ct);

        // R = z @ w_rec^T, separate accumulators, ascending k
        unsigned m0 = __ballot_sync(0xffffffffu, z0);
        unsigned m1 = __ballot_sync(0xffffffffu, z1);
        unsigned m2 = __ballot_sync(0xffffffffu, z2);
        unsigned m3 = __ballot_sync(0xffffffffu, z3);
        float R0 = 0.f, R1 = 0.f, R2 = 0.f, R3 = 0.f;
        while (m0) {  // k = 0..31
            int k = __ffs((int)m0) - 1; m0 &= m0 - 1;
            float4 q = wr4[k * 32 + lane];
            R0 = __fadd_rn(R0, q.x); R1 = __fadd_rn(R1, q.y);
            R2 = __fadd_rn(R2, q.z); R3 = __fadd_rn(R3, q.w);
        }
        while (m1) {  // k = 32..63
            int k = 32 + __ffs((int)m1) - 1; m1 &= m1 - 1;
            float4 q = wr4[k * 32 + lane];
            R0 = __fadd_rn(R0, q.x); R1 = __fadd_rn(R1, q.y);
            R2 = __fadd_rn(R2, q.z); R3 = __fadd_rn(R3, q.w);
        }
        while (m2) {  // k = 64..95
            int k = 64 + __ffs((int)m2) - 1; m2 &= m2 - 1;
            float4 q = wr4[k * 32 + lane];
            R0 = __fadd_rn(R0, q.x); R1 = __fadd_rn(R1, q.y);
            R2 = __fadd_rn(R2, q.z); R3 = __fadd_rn(R3, q.w);
        }
        while (m3) {  // k = 96..127
            int k = 96 + __ffs((int)m3) - 1; m3 &= m3 - 1;
            float4 q = wr4[k * 32 + lane];
            R0 = __fadd_rn(R0, q.x); R1 = __fadd_rn(R1, q.y);
            R2 = __fadd_rn(R2, q.z); R3 = __fadd_rn(R3, q.w);
        }
        // i_new = (i_dec + A) + R   (reference association)
        i0 = __fadd_rn(__fadd_rn(id0, xc0), R0);
        i1 = __fadd_rn(__fadd_rn(id1, xc1), R1);
        i2 = __fadd_rn(__fadd_rn(id2, xc2), R2);
        i3 = __fadd_rn(__fadd_rn(id3, xc3), R3);
    }

    // Readout: vo[o] = sum_h acc[h]*w_out[o][h]; h = r*32+lane
    float vo[OUT_DIM];
#pragma unroll
    for (int o = 0; o < OUT_DIM; ++o) {
        const float* wp = &wo[o * HID];
        float p = a0 * wp[lane] + a1 * wp[32 + lane] + a2 * wp[64 + lane] +
                  a3 * wp[96 + lane];
#pragma unroll
        for (int s = 16; s; s >>= 1) p += __shfl_xor_sync(0xffffffffu, p, s);
        vo[o] = p;
    }
    if (lane == 0) {
        float mx = vo[0];
#pragma unroll
        for (int o = 1; o < OUT_DIM; ++o) mx = fmaxf(mx, vo[o]);
        float se = 0.f;
#pragma unroll
        for (int o = 0; o < OUT_DIM; ++o) se += expf(vo[o] - mx);
        float lse = mx + logf(se);
#pragma unroll
        for (int o = 0; o < OUT_DIM; ++o) out[b * OUT_DIM + o] = vo[o] - lse;
    }
}

extern "C" void kernel_launch(void* const* d_in, const int* in_sizes, int n_in,
                              void* d_out, int out_size) {
    const float* x     = (const float*)d_in[0];
    const float* w_in  = (const float*)d_in[1];
    const float* w_rec = (const float*)d_in[2];
    const float* w_out = (const float*)d_in[3];
    float* out = (float*)d_out;

    cudaFuncSetAttribute(gemm_in, cudaFuncAttributeMaxDynamicSharedMemorySize,
                         GEMM_SMEM);
    cudaFuncSetAttribute(sim_kernel, cudaFuncAttributeMaxDynamicSharedMemorySize,
                         SIM_SMEM);

    coef_kernel<<<1, 32>>>();
    gemm_in<<<(T_STEPS * BATCH) / 128, 256, GEMM_SMEM>>>(x, w_in);
    sim_kernel<<<BATCH / 8, 256, SIM_SMEM>>>(w_rec, w_out, out);
}

// round 3
// speedup vs baseline: 1.0966x; 1.0966x over previous
#include <cuda_runtime.h>
#include <math.h>

#define T_STEPS 1000
#define BATCH   1024
#define IN_DIM  80
#define HID     128
#define OUT_DIM 10

// Precomputed input GEMM: xw[t][b][h] = sum_k x[t][b][k] * w_in[h][k]
__device__ float g_xw[(size_t)T_STEPS * BATCH * HID];   // 524 MB (BSS)
__device__ float g_coef[T_STEPS];

// ---------------------------------------------------------------------------
// Readout coefficients, closed form of the recurrence
//   c_u = a_u + 0.8*c_{u+1}, a_u = 0.1*0.9^{T-1-u}  =>  c_u = 0.9^(T-u) - 0.8^(T-u)
// (double-precision closed form ≡ serial recurrence to ~1e-13; feeds only the
// smooth readout path). Parallel: one thread per u.
// ---------------------------------------------------------------------------
__global__ void coef_kernel() {
    int u = blockIdx.x * blockDim.x + threadIdx.x;
    if (u < T_STEPS) {
        double n = (double)(T_STEPS - u);
        g_coef[u] = (float)(pow(0.9, n) - pow(0.8, n));
    }
}

// ---------------------------------------------------------------------------
// Packed-fp32 FMA helpers (sm_100+ f32x2: each half is an independent IEEE
// fp32 FMA — bitwise identical to scalar FFMA chains).
// ---------------------------------------------------------------------------
__device__ __forceinline__ unsigned long long pk2(float lo, float hi) {
    unsigned long long r;
    asm("mov.b64 %0, {%1, %2};" : "=l"(r) : "f"(lo), "f"(hi));
    return r;
}
__device__ __forceinline__ unsigned long long ffma2(unsigned long long a,
                                                    unsigned long long b,
                                                    unsigned long long c) {
    unsigned long long d;
    asm("fma.rn.f32x2 %0, %1, %2, %3;" : "=l"(d) : "l"(a), "l"(b), "l"(c));
    return d;
}
__device__ __forceinline__ void upk2(unsigned long long v, float& lo, float& hi) {
    asm("mov.b64 {%0, %1}, %2;" : "=f"(lo), "=f"(hi) : "l"(v));
}

// ---------------------------------------------------------------------------
// Input GEMM: (T*B, IN) @ (IN, H) -> g_xw, fp32, serial ascending-k chain per
// output element (numerics identical to R2 version; FFMA2 = 2 independent
// lanes). Tile: 128x128 per 256-thread CTA, 8x8 microtile, rows paired into
// f32x2 lanes (acc pair = rows 2i,2i+1 of the microtile).
// ---------------------------------------------------------------------------
#define XS_STR 84
#define WS_STR 81
#define GEMM_SMEM ((128 * XS_STR + 128 * WS_STR) * 4)

__global__ __launch_bounds__(256, 2)
void gemm_in(const float* __restrict__ x, const float* __restrict__ w) {
    extern __shared__ float sm[];
    float* xs = sm;                 // [128][XS_STR]
    float* ws = sm + 128 * XS_STR;  // [128][WS_STR]
    int tid = threadIdx.x;
    size_t rowbase = (size_t)blockIdx.x * 128;

    const float4* xg = (const float4*)(x + rowbase * IN_DIM);
#pragma unroll
    for (int it = 0; it < 10; ++it) {
        int e = tid + it * 256;
        int row = e / 20, c4 = e % 20;
        float4 v = xg[e];
        *(float4*)&xs[row * XS_STR + c4 * 4] = v;
    }
    for (int e = tid; e < HID * IN_DIM; e += 256)
        ws[(e / IN_DIM) * WS_STR + (e % IN_DIM)] = w[e];
    __syncthreads();

    int mrow = (tid >> 4) * 8;
    int mcol = tid & 15;

    // acc2[p][j]: packed pair (row 2p, row 2p+1) x col (mcol + 16*j)
    unsigned long long acc2[4][8];
#pragma unroll
    for (int p = 0; p < 4; p++)
#pragma unroll
        for (int j = 0; j < 8; j++) acc2[p][j] = pk2(0.f, 0.f);

#pragma unroll 4
    for (int k = 0; k < IN_DIM; ++k) {
        unsigned long long a2[4], b2[8];
#pragma unroll
        for (int p = 0; p < 4; p++)
            a2[p] = pk2(xs[(mrow + 2 * p) * XS_STR + k],
                        xs[(mrow + 2 * p + 1) * XS_STR + k]);
#pragma unroll
        for (int j = 0; j < 8; j++) {
            float bv = ws[(mcol + 16 * j) * WS_STR + k];
            b2[j] = pk2(bv, bv);
        }
#pragma unroll
        for (int p = 0; p < 4; p++)
#pragma unroll
            for (int j = 0; j < 8; j++)
                acc2[p][j] = ffma2(a2[p], b2[j], acc2[p][j]);
    }

    float* op = g_xw + rowbase * HID;
#pragma unroll
    for (int p = 0; p < 4; p++)
#pragma unroll
        for (int j = 0; j < 8; j++) {
            float lo, hi;
            upk2(acc2[p][j], lo, hi);
            op[(mrow + 2 * p) * HID + mcol + 16 * j] = lo;
            op[(mrow + 2 * p + 1) * HID + mcol + 16 * j] = hi;
        }
}

// ---------------------------------------------------------------------------
// Persistent simulation (UNCHANGED numerics from R2 — bit-exact path).
// One warp per batch element; h = r*32 + lane; ballot-driven sparse column
// accumulation in ascending-k order; i = (i_dec + xw) + R association.
// ---------------------------------------------------------------------------
#define SIM_SMEM ((HID * HID + T_STEPS + OUT_DIM * HID) * 4)

__global__ __launch_bounds__(256, 1)
void sim_kernel(const float* __restrict__ wrec, const float* __restrict__ wout,
                float* __restrict__ out) {
    extern __shared__ float sm[];
    float* wrp = sm;                 // permuted w_rec^T, 128*128
    float* cf  = wrp + HID * HID;    // [1000]
    float* wo  = cf + T_STEPS;       // [10][128]
    int tid = threadIdx.x, lane = tid & 31, wid = tid >> 5;
    int b = blockIdx.x * 8 + wid;

    for (int e = tid; e < HID * HID; e += 256) {
        int k = e >> 7, j = e & 127;
        int ln = j >> 2, r = j & 3;
        wrp[e] = wrec[(r * 32 + ln) * HID + k];
    }
    for (int e = tid; e < T_STEPS; e += 256) cf[e] = g_coef[e];
    for (int e = tid; e < OUT_DIM * HID; e += 256) wo[e] = wout[e];
    __syncthreads();

    float v0 = 0.f, v1 = 0.f, v2 = 0.f, v3 = 0.f;
    float i0 = 0.f, i1 = 0.f, i2 = 0.f, i3 = 0.f;
    float a0 = 0.f, a1 = 0.f, a2 = 0.f, a3 = 0.f;

    const float* xwp = g_xw + (size_t)b * HID + lane;
    const size_t tstride = (size_t)BATCH * HID;
    const float4* wr4 = (const float4*)wrp;

    float xn0 = xwp[0], xn1 = xwp[32], xn2 = xwp[64], xn3 = xwp[96];

    for (int t = 0; t < T_STEPS; ++t) {
        float xc0 = xn0, xc1 = xn1, xc2 = xn2, xc3 = xn3;
        if (t + 1 < T_STEPS) {
            const float* p = xwp + (size_t)(t + 1) * tstride;
            xn0 = p[0]; xn1 = p[32]; xn2 = p[64]; xn3 = p[96];
        }
        float ct = cf[t];

        float vd0 = __fadd_rn(v0, __fmul_rn(0.1f, __fadd_rn(__fsub_rn(0.f, v0), i0)));
        float vd1 = __fadd_rn(v1, __fmul_rn(0.1f, __fadd_rn(__fsub_rn(0.f, v1), i1)));
        float vd2 = __fadd_rn(v2, __fmul_rn(0.1f, __fadd_rn(__fsub_rn(0.f, v2), i2)));
        float vd3 = __fadd_rn(v3, __fmul_rn(0.1f, __fadd_rn(__fsub_rn(0.f, v3), i3)));
        float id0 = __fsub_rn(i0, __fmul_rn(0.2f, i0));
        float id1 = __fsub_rn(i1, __fmul_rn(0.2f, i1));
        float id2 = __fsub_rn(i2, __fmul_rn(0.2f, i2));
        float id3 = __fsub_rn(i3, __fmul_rn(0.2f, i3));
        bool z0 = __fsub_rn(vd0, 1.0f) > 0.0f;
        bool z1 = __fsub_rn(vd1, 1.0f) > 0.0f;
        bool z2 = __fsub_rn(vd2, 1.0f) > 0.0f;
        bool z3 = __fsub_rn(vd3, 1.0f) > 0.0f;
        v0 = z0 ? 0.0f : vd0;
        v1 = z1 ? 0.0f : vd1;
        v2 = z2 ? 0.0f : vd2;
        v3 = z3 ? 0.0f : vd3;
        if (z0) a0 = __fadd_rn(a0, ct);
        if (z1) a1 = __fadd_rn(a1, ct);
        if (z2) a2 = __fadd_rn(a2, ct);
        if (z3) a3 = __fadd_rn(a3, ct);

        unsigned m0 = __ballot_sync(0xffffffffu, z0);
        unsigned m1 = __ballot_sync(0xffffffffu, z1);
        unsigned m2 = __ballot_sync(0xffffffffu, z2);
        unsigned m3 = __ballot_sync(0xffffffffu, z3);
        float R0 = 0.f, R1 = 0.f, R2 = 0.f, R3 = 0.f;
        while (m0) {
            int k = __ffs((int)m0) - 1; m0 &= m0 - 1;
            float4 q = wr4[k * 32 + lane];
            R0 = __fadd_rn(R0, q.x); R1 = __fadd_rn(R1, q.y);
            R2 = __fadd_rn(R2, q.z); R3 = __fadd_rn(R3, q.w);
        }
        while (m1) {
            int k = 32 + __ffs((int)m1) - 1; m1 &= m1 - 1;
            float4 q = wr4[k * 32 + lane];
            R0 = __fadd_rn(R0, q.x); R1 = __fadd_rn(R1, q.y);
            R2 = __fadd_rn(R2, q.z); R3 = __fadd_rn(R3, q.w);
        }
        while (m2) {
            int k = 64 + __ffs((int)m2) - 1; m2 &= m2 - 1;
            float4 q = wr4[k * 32 + lane];
            R0 = __fadd_rn(R0, q.x); R1 = __fadd_rn(R1, q.y);
            R2 = __fadd_rn(R2, q.z); R3 = __fadd_rn(R3, q.w);
        }
        while (m3) {
            int k = 96 + __ffs((int)m3) - 1; m3 &= m3 - 1;
            float4 q = wr4[k * 32 + lane];
            R0 = __fadd_rn(R0, q.x); R1 = __fadd_rn(R1, q.y);
            R2 = __fadd_rn(R2, q.z); R3 = __fadd_rn(R3, q.w);
        }
        i0 = __fadd_rn(__fadd_rn(id0, xc0), R0);
        i1 = __fadd_rn(__fadd_rn(id1, xc1), R1);
        i2 = __fadd_rn(__fadd_rn(id2, xc2), R2);
        i3 = __fadd_rn(__fadd_rn(id3, xc3), R3);
    }

    float vo[OUT_DIM];
#pragma unroll
    for (int o = 0; o < OUT_DIM; ++o) {
        const float* wp = &wo[o * HID];
        float p = a0 * wp[lane] + a1 * wp[32 + lane] + a2 * wp[64 + lane] +
                  a3 * wp[96 + lane];
#pragma unroll
        for (int s = 16; s; s >>= 1) p += __shfl_xor_sync(0xffffffffu, p, s);
        vo[o] = p;
    }
    if (lane == 0) {
        float mx = vo[0];
#pragma unroll
        for (int o = 1; o < OUT_DIM; ++o) mx = fmaxf(mx, vo[o]);
        float se = 0.f;
#pragma unroll
        for (int o = 0; o < OUT_DIM; ++o) se += expf(vo[o] - mx);
        float lse = mx + logf(se);
#pragma unroll
        for (int o = 0; o < OUT_DIM; ++o) out[b * OUT_DIM + o] = vo[o] - lse;
    }
}

extern "C" void kernel_launch(void* const* d_in, const int* in_sizes, int n_in,
                              void* d_out, int out_size) {
    const float* x     = (const float*)d_in[0];
    const float* w_in  = (const float*)d_in[1];
    const float* w_rec = (const float*)d_in[2];
    const float* w_out = (const float*)d_in[3];
    float* out = (float*)d_out;

    cudaFuncSetAttribute(gemm_in, cudaFuncAttributeMaxDynamicSharedMemorySize,
                         GEMM_SMEM);
    cudaFuncSetAttribute(sim_kernel, cudaFuncAttributeMaxDynamicSharedMemorySize,
                         SIM_SMEM);

    coef_kernel<<<4, 256>>>();
    gemm_in<<<(T_STEPS * BATCH) / 128, 256, GEMM_SMEM>>>(x, w_in);
    sim_kernel<<<BATCH / 8, 256, SIM_SMEM>>>(w_rec, w_out, out);
}